// round 1
// baseline (speedup 1.0000x reference)
#include <cuda_runtime.h>
#include <math.h>

#define BB 16
#define LS 2048
#define DD 128

// ---------------- scratch (device globals; no allocations) ----------------
__device__ float g_P[(size_t)BB * LS * LS];       // exp(score) or 0, 268MB
__device__ float g_Kemb[(size_t)BB * LS * DD];    // gathered time_emb
__device__ float g_part[(size_t)BB * LS * DD];    // GEMM2 k-split partial
__device__ float g_denom[BB * LS];
__device__ float g_inv[BB * LS];
__device__ float g_c[BB * DD];                    // degenerate-column constant
__device__ unsigned char g_m[BB * LS];            // cleaned pad mask
__device__ int g_maskmode;

// ---------------- mask dtype autodetect -----------------------------------
// bool input may be delivered as uint8 (packed 1B), int32 (0/1) or float32
// (0.0/1.0). Reading the first BB*LS/4 ints is in-bounds for all three.
__global__ void ta_detect(const unsigned int* m) {
    __shared__ int sFloat, sBig;
    if (threadIdx.x == 0) { sFloat = 0; sBig = 0; }
    __syncthreads();
    int f = 0, bg = 0;
    for (int i = threadIdx.x; i < (BB * LS) / 4; i += blockDim.x) {
        unsigned v = m[i];
        if (v == 0x3F800000u) f = 1;
        else if (v > 1u) bg = 1;
    }
    if (f) atomicOr(&sFloat, 1);
    if (bg) atomicOr(&sBig, 1);
    __syncthreads();
    if (threadIdx.x == 0) g_maskmode = sFloat ? 2 : (sBig ? 1 : 0);
}

__global__ void ta_buildmask(const void* mraw) {
    int i = blockIdx.x * blockDim.x + threadIdx.x;
    if (i >= BB * LS) return;
    int mode = g_maskmode;
    unsigned char v;
    if (mode == 1) v = ((const unsigned char*)mraw)[i] ? 1 : 0;
    else           v = ((const unsigned int*)mraw)[i] ? 1 : 0;
    g_m[i] = v;
}

// ---------------- gather K = time_emb[idx] --------------------------------
__global__ void ta_gather(const int* __restrict__ ci, const float* __restrict__ te) {
    int i = blockIdx.x * blockDim.x + threadIdx.x;   // over BB*LS*DD
    int row = i >> 7;
    int c = i & 127;
    g_Kemb[i] = te[ci[row] * DD + c];
}

// ---------------- GEMM1: P = masked exp(Q.K^T / temp) ---------------------
// 64q x 64k tile, K=128 staged in two 64-chunks. Thread 4x4 frag.
__global__ void __launch_bounds__(256) ta_gemm1(const float* __restrict__ Q) {
    __shared__ float Qs[64 * 68];   // [kk][q], pitch 68
    __shared__ float Ks[64 * 68];   // [kk][k], pitch 68
    int b = blockIdx.z, qb = blockIdx.y * 64, kb = blockIdx.x * 64;
    int t = threadIdx.x;
    const size_t pbase = ((size_t)b * LS + qb) * LS + kb;

    if (kb >= qb + 64) {
        // whole tile is strictly-future-masked: write zeros, skip compute
        float4 z = make_float4(0.f, 0.f, 0.f, 0.f);
        #pragma unroll
        for (int it = 0; it < 4; it++) {
            int idx = it * 256 + t;          // 1024 float4 = 64 x 16
            int r = idx >> 4, c4 = idx & 15;
            *(float4*)&g_P[pbase + (size_t)r * LS + (c4 << 2)] = z;
        }
        return;
    }

    int tx = t & 15, ty = t >> 4;
    float acc[4][4];
    #pragma unroll
    for (int i = 0; i < 4; i++)
        #pragma unroll
        for (int j = 0; j < 4; j++) acc[i][j] = 0.f;

    const float* Qg = Q + ((size_t)b * LS + qb) * DD;
    const float* Kg = g_Kemb + ((size_t)b * LS + kb) * DD;

    for (int kc = 0; kc < DD; kc += 64) {
        #pragma unroll
        for (int it = 0; it < 16; it++) {
            int idx = it * 256 + t;          // 4096 elems: kk fast, coalesced
            int kk = idx & 63, r = idx >> 6;
            Qs[kk * 68 + r] = Qg[r * DD + kc + kk];
            Ks[kk * 68 + r] = Kg[r * DD + kc + kk];
        }
        __syncthreads();
        #pragma unroll 4
        for (int kk = 0; kk < 64; kk++) {
            float4 a4 = *(const float4*)&Qs[kk * 68 + (ty << 2)];
            float4 b4 = *(const float4*)&Ks[kk * 68 + (tx << 2)];
            float av[4] = {a4.x, a4.y, a4.z, a4.w};
            float bv[4] = {b4.x, b4.y, b4.z, b4.w};
            #pragma unroll
            for (int i = 0; i < 4; i++)
                #pragma unroll
                for (int j = 0; j < 4; j++)
                    acc[i][j] = fmaf(av[i], bv[j], acc[i][j]);
        }
        __syncthreads();
    }

    const float invtemp = 1.0f / (sqrtf((float)DD) + 1e-6f);
    #pragma unroll
    for (int i = 0; i < 4; i++) {
        int q = qb + (ty << 2) + i;
        int pm = g_m[b * LS + q];
        float r[4];
        #pragma unroll
        for (int j = 0; j < 4; j++) {
            int k = kb + (tx << 2) + j;
            r[j] = (pm || k > q) ? 0.0f : expf(acc[i][j] * invtemp);
        }
        *(float4*)&g_P[pbase + (size_t)((ty << 2) + i) * LS + (tx << 2)] =
            make_float4(r[0], r[1], r[2], r[3]);
    }
}

// ---------------- column sums (softmax denominators over q) ---------------
__global__ void ta_colsum() {
    int k = blockIdx.x * 256 + threadIdx.x;
    int b = blockIdx.y;
    const float* p = g_P + (size_t)b * LS * LS + k;
    float s0 = 0.f, s1 = 0.f, s2 = 0.f, s3 = 0.f;
    for (int q = 0; q < LS; q += 4) {
        s0 += p[(size_t)q * LS];
        s1 += p[(size_t)(q + 1) * LS];
        s2 += p[(size_t)(q + 2) * LS];
        s3 += p[(size_t)(q + 3) * LS];
    }
    g_denom[b * LS + k] = (s0 + s1) + (s2 + s3);
}

__global__ void ta_inv() {
    int i = blockIdx.x * blockDim.x + threadIdx.x;
    if (i >= BB * LS) return;
    float d = g_denom[i];
    g_inv[i] = (d != 0.0f) ? 1.0f / d : 0.0f;   // 0 marks degenerate column
}

// c[b,d] = (1/L) * sum over degenerate k of V[b,k,d]
__global__ void ta_cvec(const float* __restrict__ V) {
    int b = blockIdx.x, d = threadIdx.x;
    float s = 0.f;
    for (int k = 0; k < LS; k++)
        if (g_denom[b * LS + k] == 0.0f)
            s += V[((size_t)b * LS + k) * DD + d];
    g_c[b * DD + d] = s * (1.0f / (float)LS);
}

// ---------------- GEMM2: out = (P*inv) . V + c ----------------------------
// 128q x 128d tile, k chunks of 16, 2-way k-split across blockIdx.y for
// load balance on the triangular k-range. kz=1 writes partials to g_part.
__global__ void __launch_bounds__(256) ta_gemm2(const float* __restrict__ V,
                                                float* __restrict__ out) {
    __shared__ float Ws[16 * 132];   // [kk][q], pitch 132
    __shared__ float Vs[16 * 128];   // [kk][d]
    int qt = blockIdx.x, kz = blockIdx.y, b = blockIdx.z;
    int qb = qt * 128;
    int t = threadIdx.x, tx = t & 15, ty = t >> 4;

    int nch = (qb >> 4) + 8;            // chunks of 16 up to k <= qb+127
    int half = (nch + 1) >> 1;
    int c0 = kz ? half : 0;
    int c1 = kz ? nch : half;

    float acc[8][8];
    #pragma unroll
    for (int i = 0; i < 8; i++)
        #pragma unroll
        for (int j = 0; j < 8; j++) acc[i][j] = 0.f;

    const size_t pb = ((size_t)b * LS + qb) * LS;

    for (int ch = c0; ch < c1; ch++) {
        int kc = ch << 4;
        #pragma unroll
        for (int it = 0; it < 8; it++) {
            int idx = it * 256 + t;      // 2048 elems of P tile [128q][16k]
            int kk = idx & 15, r = idx >> 4;
            Ws[kk * 132 + r] = g_P[pb + (size_t)r * LS + kc + kk] *
                               g_inv[b * LS + kc + kk];
        }
        #pragma unroll
        for (int it = 0; it < 2; it++) {
            int idx = it * 256 + t;      // 512 float4 of V tile [16k][128d]
            int kk = idx >> 5, c4 = idx & 31;
            *(float4*)&Vs[kk * 128 + (c4 << 2)] =
                *(const float4*)&V[((size_t)b * LS + kc + kk) * DD + (c4 << 2)];
        }
        __syncthreads();
        #pragma unroll
        for (int kk = 0; kk < 16; kk++) {
            float4 a0 = *(const float4*)&Ws[kk * 132 + (ty << 2)];
            float4 a1 = *(const float4*)&Ws[kk * 132 + 64 + (ty << 2)];
            float4 v0 = *(const float4*)&Vs[kk * 128 + (tx << 2)];
            float4 v1 = *(const float4*)&Vs[kk * 128 + 64 + (tx << 2)];
            float av[8] = {a0.x, a0.y, a0.z, a0.w, a1.x, a1.y, a1.z, a1.w};
            float vv[8] = {v0.x, v0.y, v0.z, v0.w, v1.x, v1.y, v1.z, v1.w};
            #pragma unroll
            for (int i = 0; i < 8; i++)
                #pragma unroll
                for (int j = 0; j < 8; j++)
                    acc[i][j] = fmaf(av[i], vv[j], acc[i][j]);
        }
        __syncthreads();
    }

    if (kz == 0) {
        float cf[8];
        #pragma unroll
        for (int j = 0; j < 8; j++) {
            int d = (j < 4) ? (tx << 2) + j : 64 + (tx << 2) + j - 4;
            cf[j] = g_c[b * DD + d];
        }
        #pragma unroll
        for (int i = 0; i < 8; i++) {
            int q = qb + ((i < 4) ? (ty << 2) + i : 64 + (ty << 2) + i - 4);
            float4 r0 = make_float4(acc[i][0] + cf[0], acc[i][1] + cf[1],
                                    acc[i][2] + cf[2], acc[i][3] + cf[3]);
            float4 r1 = make_float4(acc[i][4] + cf[4], acc[i][5] + cf[5],
                                    acc[i][6] + cf[6], acc[i][7] + cf[7]);
            *(float4*)&out[((size_t)b * LS + q) * DD + (tx << 2)] = r0;
            *(float4*)&out[((size_t)b * LS + q) * DD + 64 + (tx << 2)] = r1;
        }
    } else {
        #pragma unroll
        for (int i = 0; i < 8; i++) {
            int q = qb + ((i < 4) ? (ty << 2) + i : 64 + (ty << 2) + i - 4);
            float4 r0 = make_float4(acc[i][0], acc[i][1], acc[i][2], acc[i][3]);
            float4 r1 = make_float4(acc[i][4], acc[i][5], acc[i][6], acc[i][7]);
            *(float4*)&g_part[((size_t)b * LS + q) * DD + (tx << 2)] = r0;
            *(float4*)&g_part[((size_t)b * LS + q) * DD + 64 + (tx << 2)] = r1;
        }
    }
}

__global__ void ta_add(float* __restrict__ out) {
    int i = blockIdx.x * blockDim.x + threadIdx.x;   // over BB*LS*DD
    out[i] += g_part[i];
}

// ---------------- launch ---------------------------------------------------
extern "C" void kernel_launch(void* const* d_in, const int* in_sizes, int n_in,
                              void* d_out, int out_size) {
    const int*   ci = (const int*)d_in[0];
    const float* qv = (const float*)d_in[1];   // cas_embs = Q = V
    const void*  mk = d_in[2];
    const float* te = (const float*)d_in[3];
    float* out = (float*)d_out;

    ta_detect<<<1, 256>>>((const unsigned int*)mk);
    ta_buildmask<<<(BB * LS) / 256, 256>>>(mk);
    ta_gather<<<(BB * LS * DD) / 256, 256>>>(ci, te);
    ta_gemm1<<<dim3(LS / 64, LS / 64, BB), 256>>>(qv);
    ta_colsum<<<dim3(LS / 256, BB), 256>>>();
    ta_inv<<<(BB * LS) / 256, 256>>>();
    ta_cvec<<<BB, DD>>>(qv);
    ta_gemm2<<<dim3(LS / 128, 2, BB), 256>>>(qv, out);
    ta_add<<<(BB * LS * DD) / 256, 256>>>(out);
}

// round 2
// speedup vs baseline: 1.0460x; 1.0460x over previous
#include <cuda_runtime.h>
#include <math.h>

#define BB 16
#define LS 2048
#define DD 128

// ---------------- scratch (device globals; no allocations) ----------------
__device__ float g_P[(size_t)BB * LS * LS];       // exp(score); upper tiles never written/read
__device__ float g_Kemb[(size_t)BB * LS * DD];    // gathered time_emb
__device__ float g_part[(size_t)BB * LS * DD];    // GEMM2 k-split partial
__device__ float g_denom[BB * LS];
__device__ float g_inv[BB * LS];
__device__ float g_c[BB * DD];                    // degenerate-column constant
__device__ unsigned char g_m[BB * LS];            // cleaned pad mask
__device__ int g_maskmode;

// ---------------- mask dtype autodetect -----------------------------------
__global__ void ta_detect(const unsigned int* m) {
    __shared__ int sFloat, sBig;
    if (threadIdx.x == 0) { sFloat = 0; sBig = 0; }
    __syncthreads();
    int f = 0, bg = 0;
    for (int i = threadIdx.x; i < (BB * LS) / 4; i += blockDim.x) {
        unsigned v = m[i];
        if (v == 0x3F800000u) f = 1;
        else if (v > 1u) bg = 1;
    }
    if (f) atomicOr(&sFloat, 1);
    if (bg) atomicOr(&sBig, 1);
    __syncthreads();
    if (threadIdx.x == 0) g_maskmode = sFloat ? 2 : (sBig ? 1 : 0);
}

__global__ void ta_buildmask(const void* mraw) {
    int i = blockIdx.x * blockDim.x + threadIdx.x;
    if (i >= BB * LS) return;
    int mode = g_maskmode;
    unsigned char v;
    if (mode == 1) v = ((const unsigned char*)mraw)[i] ? 1 : 0;
    else           v = ((const unsigned int*)mraw)[i] ? 1 : 0;
    g_m[i] = v;
}

// ---------------- gather K = time_emb[idx] --------------------------------
__global__ void ta_gather(const int* __restrict__ ci, const float* __restrict__ te) {
    int i = blockIdx.x * blockDim.x + threadIdx.x;   // over BB*LS*DD
    int row = i >> 7;
    int c = i & 127;
    g_Kemb[i] = te[ci[row] * DD + c];
}

// ---------------- GEMM1: P = masked exp(Q.K^T / temp) ---------------------
// 128q x 128k tile, 8x8 register frags, K staged in 16-chunks.
// Only lower-triangular tiles (kt <= qt) are computed or written.
__global__ void __launch_bounds__(256) ta_gemm1(const float* __restrict__ Q) {
    int qt = blockIdx.y, kt = blockIdx.x, b = blockIdx.z;
    if (kt > qt) return;                 // never read downstream
    int qb = qt << 7, kb = kt << 7;
    __shared__ float Qs[16 * 132];       // [kk][q], pitch 132
    __shared__ float Ks[16 * 132];       // [kk][k]
    int t = threadIdx.x, tx = t & 15, ty = t >> 4;

    float acc[8][8];
    #pragma unroll
    for (int i = 0; i < 8; i++)
        #pragma unroll
        for (int j = 0; j < 8; j++) acc[i][j] = 0.f;

    const float* Qg = Q + ((size_t)b * LS + qb) * DD;
    const float* Kg = g_Kemb + ((size_t)b * LS + kb) * DD;

    for (int kc = 0; kc < DD; kc += 16) {
        #pragma unroll
        for (int it = 0; it < 8; it++) {
            int idx = it * 256 + t;          // 2048 = 128 rows x 16 k
            int kk = idx & 15, r = idx >> 4;
            Qs[kk * 132 + r] = Qg[(size_t)r * DD + kc + kk];
            Ks[kk * 132 + r] = Kg[(size_t)r * DD + kc + kk];
        }
        __syncthreads();
        #pragma unroll
        for (int kk = 0; kk < 16; kk++) {
            float4 a0 = *(const float4*)&Qs[kk * 132 + (ty << 2)];
            float4 a1 = *(const float4*)&Qs[kk * 132 + 64 + (ty << 2)];
            float4 b0 = *(const float4*)&Ks[kk * 132 + (tx << 2)];
            float4 b1 = *(const float4*)&Ks[kk * 132 + 64 + (tx << 2)];
            float av[8] = {a0.x, a0.y, a0.z, a0.w, a1.x, a1.y, a1.z, a1.w};
            float bv[8] = {b0.x, b0.y, b0.z, b0.w, b1.x, b1.y, b1.z, b1.w};
            #pragma unroll
            for (int i = 0; i < 8; i++)
                #pragma unroll
                for (int j = 0; j < 8; j++)
                    acc[i][j] = fmaf(av[i], bv[j], acc[i][j]);
        }
        __syncthreads();
    }

    const float invtemp = 1.0f / (sqrtf((float)DD) + 1e-6f);
    const size_t pbase = ((size_t)b * LS + qb) * LS + kb;
    #pragma unroll
    for (int i = 0; i < 8; i++) {
        int qr = ((i < 4) ? (ty << 2) + i : 64 + (ty << 2) + i - 4);
        int q = qb + qr;
        int pm = g_m[b * LS + q];
        float r[8];
        #pragma unroll
        for (int j = 0; j < 8; j++) {
            int kr = ((j < 4) ? (tx << 2) + j : 64 + (tx << 2) + j - 4);
            int k = kb + kr;
            r[j] = (pm || k > q) ? 0.0f : __expf(acc[i][j] * invtemp);
        }
        *(float4*)&g_P[pbase + (size_t)qr * LS + (tx << 2)] =
            make_float4(r[0], r[1], r[2], r[3]);
        *(float4*)&g_P[pbase + (size_t)qr * LS + 64 + (tx << 2)] =
            make_float4(r[4], r[5], r[6], r[7]);
    }
}

// ---------------- column sums (softmax denominators over q) ---------------
// P[q,k] == 0 for q < k within written tiles; tiles with qt < kt were never
// written, so start the q-loop at the k-tile boundary.
__global__ void ta_colsum() {
    int k = blockIdx.x * 256 + threadIdx.x;
    int b = blockIdx.y;
    int q0 = (k >> 7) << 7;
    const float* p = g_P + (size_t)b * LS * LS + k;
    float s0 = 0.f, s1 = 0.f, s2 = 0.f, s3 = 0.f;
    for (int q = q0; q < LS; q += 4) {
        s0 += p[(size_t)q * LS];
        s1 += p[(size_t)(q + 1) * LS];
        s2 += p[(size_t)(q + 2) * LS];
        s3 += p[(size_t)(q + 3) * LS];
    }
    g_denom[b * LS + k] = (s0 + s1) + (s2 + s3);
}

__global__ void ta_inv() {
    int i = blockIdx.x * blockDim.x + threadIdx.x;
    if (i >= BB * LS) return;
    float d = g_denom[i];
    g_inv[i] = (d != 0.0f) ? 1.0f / d : 0.0f;   // 0 marks degenerate column
}

// c[b,d] = (1/L) * sum over degenerate k of V[b,k,d]
__global__ void ta_cvec(const float* __restrict__ V) {
    int b = blockIdx.x, d = threadIdx.x;
    float s = 0.f;
    for (int k = 0; k < LS; k++)
        if (g_denom[b * LS + k] == 0.0f)
            s += V[((size_t)b * LS + k) * DD + d];
    g_c[b * DD + d] = s * (1.0f / (float)LS);
}

// ---------------- GEMM2: out = (P*inv) . V + c ----------------------------
// 128q x 128d tile, k chunks of 16, 2-way k-split for triangular balance.
__global__ void __launch_bounds__(256) ta_gemm2(const float* __restrict__ V,
                                                float* __restrict__ out) {
    __shared__ float Ws[16 * 132];   // [kk][q], pitch 132
    __shared__ float Vs[16 * 128];   // [kk][d]
    int qt = blockIdx.x, kz = blockIdx.y, b = blockIdx.z;
    int qb = qt * 128;
    int t = threadIdx.x, tx = t & 15, ty = t >> 4;

    int nch = (qb >> 4) + 8;            // chunks of 16 up to k <= qb+127
    int half = (nch + 1) >> 1;
    int c0 = kz ? half : 0;
    int c1 = kz ? nch : half;

    float acc[8][8];
    #pragma unroll
    for (int i = 0; i < 8; i++)
        #pragma unroll
        for (int j = 0; j < 8; j++) acc[i][j] = 0.f;

    const size_t pb = ((size_t)b * LS + qb) * LS;

    for (int ch = c0; ch < c1; ch++) {
        int kc = ch << 4;
        #pragma unroll
        for (int it = 0; it < 8; it++) {
            int idx = it * 256 + t;      // 2048 elems of P tile [128q][16k]
            int kk = idx & 15, r = idx >> 4;
            Ws[kk * 132 + r] = g_P[pb + (size_t)r * LS + kc + kk] *
                               g_inv[b * LS + kc + kk];
        }
        #pragma unroll
        for (int it = 0; it < 2; it++) {
            int idx = it * 256 + t;      // 512 float4 of V tile [16k][128d]
            int kk = idx >> 5, c4 = idx & 31;
            *(float4*)&Vs[kk * 128 + (c4 << 2)] =
                *(const float4*)&V[((size_t)b * LS + kc + kk) * DD + (c4 << 2)];
        }
        __syncthreads();
        #pragma unroll
        for (int kk = 0; kk < 16; kk++) {
            float4 a0 = *(const float4*)&Ws[kk * 132 + (ty << 2)];
            float4 a1 = *(const float4*)&Ws[kk * 132 + 64 + (ty << 2)];
            float4 v0 = *(const float4*)&Vs[kk * 128 + (tx << 2)];
            float4 v1 = *(const float4*)&Vs[kk * 128 + 64 + (tx << 2)];
            float av[8] = {a0.x, a0.y, a0.z, a0.w, a1.x, a1.y, a1.z, a1.w};
            float vv[8] = {v0.x, v0.y, v0.z, v0.w, v1.x, v1.y, v1.z, v1.w};
            #pragma unroll
            for (int i = 0; i < 8; i++)
                #pragma unroll
                for (int j = 0; j < 8; j++)
                    acc[i][j] = fmaf(av[i], vv[j], acc[i][j]);
        }
        __syncthreads();
    }

    if (kz == 0) {
        float cf[8];
        #pragma unroll
        for (int j = 0; j < 8; j++) {
            int d = (j < 4) ? (tx << 2) + j : 64 + (tx << 2) + j - 4;
            cf[j] = g_c[b * DD + d];
        }
        #pragma unroll
        for (int i = 0; i < 8; i++) {
            int q = qb + ((i < 4) ? (ty << 2) + i : 64 + (ty << 2) + i - 4);
            float4 r0 = make_float4(acc[i][0] + cf[0], acc[i][1] + cf[1],
                                    acc[i][2] + cf[2], acc[i][3] + cf[3]);
            float4 r1 = make_float4(acc[i][4] + cf[4], acc[i][5] + cf[5],
                                    acc[i][6] + cf[6], acc[i][7] + cf[7]);
            *(float4*)&out[((size_t)b * LS + q) * DD + (tx << 2)] = r0;
            *(float4*)&out[((size_t)b * LS + q) * DD + 64 + (tx << 2)] = r1;
        }
    } else {
        #pragma unroll
        for (int i = 0; i < 8; i++) {
            int q = qb + ((i < 4) ? (ty << 2) + i : 64 + (ty << 2) + i - 4);
            float4 r0 = make_float4(acc[i][0], acc[i][1], acc[i][2], acc[i][3]);
            float4 r1 = make_float4(acc[i][4], acc[i][5], acc[i][6], acc[i][7]);
            *(float4*)&g_part[((size_t)b * LS + q) * DD + (tx << 2)] = r0;
            *(float4*)&g_part[((size_t)b * LS + q) * DD + 64 + (tx << 2)] = r1;
        }
    }
}

__global__ void ta_add(float* __restrict__ out) {
    int i = blockIdx.x * blockDim.x + threadIdx.x;   // over BB*LS*DD
    out[i] += g_part[i];
}

// ---------------- launch ---------------------------------------------------
extern "C" void kernel_launch(void* const* d_in, const int* in_sizes, int n_in,
                              void* d_out, int out_size) {
    const int*   ci = (const int*)d_in[0];
    const float* qv = (const float*)d_in[1];   // cas_embs = Q = V
    const void*  mk = d_in[2];
    const float* te = (const float*)d_in[3];
    float* out = (float*)d_out;

    ta_detect<<<1, 256>>>((const unsigned int*)mk);
    ta_buildmask<<<(BB * LS) / 256, 256>>>(mk);
    ta_gather<<<(BB * LS * DD) / 256, 256>>>(ci, te);
    ta_gemm1<<<dim3(LS / 128, LS / 128, BB), 256>>>(qv);
    ta_colsum<<<dim3(LS / 256, BB), 256>>>();
    ta_inv<<<(BB * LS) / 256, 256>>>();
    ta_cvec<<<BB, DD>>>(qv);
    ta_gemm2<<<dim3(LS / 128, 2, BB), 256>>>(qv, out);
    ta_add<<<(BB * LS * DD) / 256, 256>>>(out);
}

// round 4
// speedup vs baseline: 2.8255x; 2.7012x over previous
#include <cuda_runtime.h>
#include <cuda_fp16.h>
#include <math.h>
#include <stdint.h>

#define BB 16
#define LS 2048
#define DD 128

// ---------------- scratch (device globals; no allocations) ----------------
__device__ __half g_Ph[(size_t)BB * LS * LS];          // P hi (134MB)
__device__ __half g_Pl[(size_t)BB * LS * LS];          // P lo (134MB)
__device__ __half g_Qh[(size_t)BB * LS * DD];
__device__ __half g_Ql[(size_t)BB * LS * DD];
__device__ __half g_Kh[(size_t)BB * LS * DD];
__device__ __half g_Kl[(size_t)BB * LS * DD];
__device__ __half g_Vth[(size_t)BB * DD * LS];         // inv[k]*V transposed, hi
__device__ __half g_Vtl[(size_t)BB * DD * LS];         // lo
__device__ float g_dpart[BB * 16 * LS];                // per-(b,qt) column partials
__device__ float g_inv[BB * LS];
__device__ float g_cpart[BB * 16 * DD];
__device__ float g_c[BB * DD];
__device__ unsigned char g_m[BB * LS];
__device__ int g_qtflag[BB * 16];                      // 1 = whole q-tile masked
__device__ int g_maskmode;

// smem layout (bytes): 4 fp16 tiles 128x64 pitch-72 elems (144B) = 18432 each
#define T_AH 0
#define T_AL 18432
#define T_BH 36864
#define T_BL 55296
#define SMEM_BYTES 74752        // tiles 73728; red buffer at 69632 overlaps BL only after mma
#define RED_OFF 73728           // 2x128 floats = 1024B
// staging: float ep[128][132] = 67584B reuses tile area after mma

// ---------------- helpers ---------------------------------------------------
__device__ __forceinline__ uint32_t smem_u32(const void* p) {
    uint32_t a;
    asm("{ .reg .u64 t; cvta.to.shared.u64 t, %1; cvt.u32.u64 %0, t; }" : "=r"(a) : "l"(p));
    return a;
}
__device__ __forceinline__ void ldsm4(uint32_t& r0, uint32_t& r1, uint32_t& r2,
                                      uint32_t& r3, uint32_t addr) {
    asm volatile("ldmatrix.sync.aligned.m8n8.x4.shared.b16 {%0,%1,%2,%3}, [%4];"
                 : "=r"(r0), "=r"(r1), "=r"(r2), "=r"(r3) : "r"(addr));
}
__device__ __forceinline__ void mma16816(float* c, const uint32_t* a, const uint32_t* b) {
    asm volatile("mma.sync.aligned.m16n8k16.row.col.f32.f16.f16.f32 "
                 "{%0,%1,%2,%3},{%4,%5,%6,%7},{%8,%9},{%0,%1,%2,%3};"
                 : "+f"(c[0]), "+f"(c[1]), "+f"(c[2]), "+f"(c[3])
                 : "r"(a[0]), "r"(a[1]), "r"(a[2]), "r"(a[3]), "r"(b[0]), "r"(b[1]));
}

// load a 128-row x 64-col fp16 tile into smem (pitch 72 elems), coalesced
__device__ __forceinline__ void load_tile(const __half* __restrict__ g,
                                          size_t rowstride, char* st, int t) {
    #pragma unroll
    for (int it = 0; it < 4; it++) {
        int idx = it * 256 + t;              // 1024 groups of 8 fp16 (16B)
        int r = idx >> 3, gp = idx & 7;
        uint4 v = *(const uint4*)(g + (size_t)r * rowstride + gp * 8);
        *(uint4*)(st + r * 144 + gp * 16) = v;
    }
}

// 3-pass (hh, h*l, l*h) mma over one 64-k chunk already in smem
__device__ __forceinline__ void mma_chunk(char* smem, int lane, int m0, int n0,
                                          float acc[2][8][4]) {
    int arow = (lane & 7) + ((lane >> 3) & 1) * 8;
    int acol = ((lane >> 4) & 1) * 8;
    int brow = (lane & 7) + ((lane >> 4) & 1) * 8;
    int bcol = ((lane >> 3) & 1) * 8;
    #pragma unroll
    for (int p = 0; p < 3; p++) {
        char* pA = smem + ((p == 2) ? T_AL : T_AH);
        char* pB = smem + ((p == 1) ? T_BL : T_BH);
        #pragma unroll
        for (int ks = 0; ks < 4; ks++) {
            int k0 = ks * 16;
            uint32_t a[8], bfr[16];
            #pragma unroll
            for (int mf = 0; mf < 2; mf++)
                ldsm4(a[mf*4], a[mf*4+1], a[mf*4+2], a[mf*4+3],
                      smem_u32(pA + (m0 + mf*16 + arow) * 144 + (k0 + acol) * 2));
            #pragma unroll
            for (int bg = 0; bg < 4; bg++)
                ldsm4(bfr[bg*4], bfr[bg*4+1], bfr[bg*4+2], bfr[bg*4+3],
                      smem_u32(pB + (n0 + bg*16 + brow) * 144 + (k0 + bcol) * 2));
            #pragma unroll
            for (int mf = 0; mf < 2; mf++)
                #pragma unroll
                for (int nf = 0; nf < 8; nf++)
                    mma16816(acc[mf][nf], &a[mf*4], &bfr[(nf >> 1) * 4 + (nf & 1) * 2]);
        }
    }
}

// ---------------- small kernels --------------------------------------------
__global__ void ta_detect(const unsigned int* m) {
    __shared__ int sF, sB;
    if (threadIdx.x == 0) { sF = 0; sB = 0; }
    __syncthreads();
    int f = 0, bg = 0;
    for (int i = threadIdx.x; i < (BB * LS) / 4; i += blockDim.x) {
        unsigned v = m[i];
        if (v == 0x3F800000u) f = 1; else if (v > 1u) bg = 1;
    }
    if (f) atomicOr(&sF, 1);
    if (bg) atomicOr(&sB, 1);
    __syncthreads();
    if (threadIdx.x == 0) g_maskmode = sF ? 2 : (sB ? 1 : 0);
}

__global__ void ta_buildmask(const void* mraw) {
    int i = blockIdx.x * blockDim.x + threadIdx.x;
    if (i >= BB * LS) return;
    int mode = g_maskmode;
    g_m[i] = (mode == 1) ? (((const unsigned char*)mraw)[i] ? 1 : 0)
                         : (((const unsigned int*)mraw)[i] ? 1 : 0);
}

__global__ void ta_qtflag() {
    int b = blockIdx.y, qt = blockIdx.x, t = threadIdx.x;
    int unmasked = (g_m[b * LS + qt * 128 + t] == 0);
    int cnt = __syncthreads_count(unmasked);
    if (t == 0) g_qtflag[b * 16 + qt] = (cnt == 0);
}

__global__ void ta_prep(const int* __restrict__ ci, const float* __restrict__ Q,
                        const float* __restrict__ te) {
    int i = blockIdx.x * blockDim.x + threadIdx.x;   // over BB*LS*DD
    int row = i >> 7, c = i & 127;
    float q = Q[i];
    __half qh = __float2half_rn(q);
    g_Qh[i] = qh; g_Ql[i] = __float2half_rn(q - __half2float(qh));
    float k = te[ci[row] * DD + c];
    __half kh = __float2half_rn(k);
    g_Kh[i] = kh; g_Kl[i] = __float2half_rn(k - __half2float(kh));
}

__global__ void ta_dred() {
    int b = blockIdx.y, kt = blockIdx.x, t = threadIdx.x;
    int k = kt * 128 + t;
    float s = 0.f;
    for (int qt = kt; qt < 16; qt++) s += g_dpart[(b * 16 + qt) * LS + k];
    g_inv[b * LS + k] = (s != 0.f) ? 1.f / s : 0.f;
}

__global__ void ta_cpart(const float* __restrict__ V) {
    int b = blockIdx.y, ch = blockIdx.x, t = threadIdx.x;
    float s = 0.f;
    for (int k2 = 0; k2 < 128; k2++) {
        int k = ch * 128 + k2;
        if (g_inv[b * LS + k] == 0.f) s += V[((size_t)(b * LS + k)) * DD + t];
    }
    g_cpart[(b * 16 + ch) * DD + t] = s;
}

__global__ void ta_cfin() {
    int b = blockIdx.x, t = threadIdx.x;
    float s = 0.f;
    for (int ch = 0; ch < 16; ch++) s += g_cpart[(b * 16 + ch) * DD + t];
    g_c[b * DD + t] = s * (1.0f / (float)LS);
}

__global__ void ta_vt(const float* __restrict__ V) {
    __shared__ float sm[32][33];
    int b = blockIdx.z, k0 = blockIdx.x * 32, d0 = blockIdx.y * 32;
    int tx = threadIdx.x, ty = threadIdx.y;    // 32 x 8
    #pragma unroll
    for (int i = 0; i < 4; i++) {
        int kk = ty + i * 8;
        sm[kk][tx] = V[((size_t)(b * LS + k0 + kk)) * DD + d0 + tx];
    }
    __syncthreads();
    #pragma unroll
    for (int i = 0; i < 4; i++) {
        int dd_ = ty + i * 8;
        int k = k0 + tx;
        float v = sm[tx][dd_] * g_inv[b * LS + k];
        __half h = __float2half_rn(v);
        __half l = __float2half_rn(v - __half2float(h));
        size_t o = ((size_t)(b * DD + d0 + dd_)) * LS + k;
        g_Vth[o] = h; g_Vtl[o] = l;
    }
}

// ---------------- GEMM1: S = Q.K^T, exp, colsum, P store -------------------
__global__ void __launch_bounds__(256, 2) ta_gemm1() {
    int x = blockIdx.x, b = blockIdx.y;
    int qt = (int)((sqrtf(8.f * x + 1.f) - 1.f) * 0.5f);
    while ((qt + 1) * (qt + 2) / 2 <= x) qt++;
    while (qt * (qt + 1) / 2 > x) qt--;
    int kt = x - qt * (qt + 1) / 2;
    int qb = qt << 7, kb = kt << 7;
    int t = threadIdx.x, lane = t & 31, wid = t >> 5;

    if (g_qtflag[b * 16 + qt]) {               // whole q-tile masked: P never read
        if (t < 128) g_dpart[(b * 16 + qt) * LS + kb + t] = 0.f;
        return;
    }

    extern __shared__ char smem[];
    int m0 = (wid & 3) * 32, n0 = (wid >> 2) * 64;
    float acc[2][8][4];
    #pragma unroll
    for (int i = 0; i < 2; i++)
        #pragma unroll
        for (int j = 0; j < 8; j++)
            #pragma unroll
            for (int v = 0; v < 4; v++) acc[i][j][v] = 0.f;

    const __half* Qh = g_Qh + ((size_t)(b * LS + qb)) * DD;
    const __half* Ql = g_Ql + ((size_t)(b * LS + qb)) * DD;
    const __half* Kh = g_Kh + ((size_t)(b * LS + kb)) * DD;
    const __half* Kl = g_Kl + ((size_t)(b * LS + kb)) * DD;

    for (int ic = 0; ic < 2; ic++) {
        int kc = ic * 64;
        __syncthreads();
        load_tile(Qh + kc, DD, smem + T_AH, t);
        load_tile(Ql + kc, DD, smem + T_AL, t);
        load_tile(Kh + kc, DD, smem + T_BH, t);
        load_tile(Kl + kc, DD, smem + T_BL, t);
        __syncthreads();
        mma_chunk(smem, lane, m0, n0, acc);
    }
    __syncthreads();

    // epilogue: mask + exp -> staged fp32 tile [128][132]
    float* ep = (float*)smem;
    int gid = lane >> 2, tid = lane & 3;
    const float invt = 1.0f / (sqrtf((float)DD) + 1e-6f);
    #pragma unroll
    for (int mf = 0; mf < 2; mf++)
        #pragma unroll
        for (int h = 0; h < 2; h++) {
            int m = m0 + mf * 16 + h * 8 + gid;
            int gq = qb + m;
            int pm = g_m[b * LS + gq];
            #pragma unroll
            for (int nf = 0; nf < 8; nf++) {
                int n = n0 + nf * 8 + tid * 2;
                int gk = kb + n;
                float v0 = acc[mf][nf][h * 2 + 0];
                float v1 = acc[mf][nf][h * 2 + 1];
                float e0 = (pm || gk > gq)     ? 0.f : __expf(v0 * invt);
                float e1 = (pm || gk + 1 > gq) ? 0.f : __expf(v1 * invt);
                ep[m * 132 + n] = e0;
                ep[m * 132 + n + 1] = e1;
            }
        }
    __syncthreads();

    // deterministic column sums (split 2x over rows)
    int col = t & 127, hf = t >> 7;
    float s = 0.f;
    #pragma unroll 8
    for (int r = 0; r < 64; r++) s += ep[(hf * 64 + r) * 132 + col];
    float* red = (float*)(smem + RED_OFF);
    red[hf * 128 + col] = s;
    __syncthreads();
    if (t < 128) g_dpart[(b * 16 + qt) * LS + kb + t] = red[t] + red[128 + t];

    // P store: fp16 hi/lo, coalesced 4B
    #pragma unroll
    for (int it = 0; it < 32; it++) {
        int idx = it * 256 + t;
        int r = idx >> 6, c0 = (idx & 63) * 2;
        float v0 = ep[r * 132 + c0];
        float v1 = ep[r * 132 + c0 + 1];
        __half h0 = __float2half_rn(v0), h1 = __float2half_rn(v1);
        __half l0 = __float2half_rn(v0 - __half2float(h0));
        __half l1 = __float2half_rn(v1 - __half2float(h1));
        size_t o = ((size_t)(b * LS + qb + r)) * LS + kb + c0;
        __half2 hp; hp.x = h0; hp.y = h1;
        __half2 lp; lp.x = l0; lp.y = l1;
        *(__half2*)&g_Ph[o] = hp;
        *(__half2*)&g_Pl[o] = lp;
    }
}

// ---------------- GEMM2: out = P . Vt + c ----------------------------------
__global__ void __launch_bounds__(256, 2) ta_gemm2(float* __restrict__ out) {
    int qt = 15 - blockIdx.x, b = blockIdx.y;
    int qb = qt << 7;
    int t = threadIdx.x, lane = t & 31, wid = t >> 5;

    if (g_qtflag[b * 16 + qt]) {               // out rows = c
        if (t < 128) {
            float cv = g_c[b * DD + t];
            for (int r = 0; r < 128; r++)
                out[((size_t)(b * LS + qb + r)) * DD + t] = cv;
        }
        return;
    }

    extern __shared__ char smem[];
    int m0 = (wid & 3) * 32, n0 = (wid >> 2) * 64;
    float acc[2][8][4];
    #pragma unroll
    for (int i = 0; i < 2; i++)
        #pragma unroll
        for (int j = 0; j < 8; j++)
            #pragma unroll
            for (int v = 0; v < 4; v++) acc[i][j][v] = 0.f;

    const __half* Ph = g_Ph + ((size_t)(b * LS + qb)) * LS;
    const __half* Pl = g_Pl + ((size_t)(b * LS + qb)) * LS;
    const __half* Vh = g_Vth + (size_t)b * DD * LS;
    const __half* Vl = g_Vtl + (size_t)b * DD * LS;

    int nck = (qt + 1) * 2;
    for (int ic = 0; ic < nck; ic++) {
        int kc = ic * 64;
        __syncthreads();
        load_tile(Ph + kc, LS, smem + T_AH, t);
        load_tile(Pl + kc, LS, smem + T_AL, t);
        load_tile(Vh + kc, LS, smem + T_BH, t);
        load_tile(Vl + kc, LS, smem + T_BL, t);
        __syncthreads();
        mma_chunk(smem, lane, m0, n0, acc);
    }

    int gid = lane >> 2, tid = lane & 3;
    #pragma unroll
    for (int mf = 0; mf < 2; mf++)
        #pragma unroll
        for (int h = 0; h < 2; h++) {
            int m = m0 + mf * 16 + h * 8 + gid;
            int gq = qb + m;
            size_t ob = ((size_t)(b * LS + gq)) * DD;
            #pragma unroll
            for (int nf = 0; nf < 8; nf++) {
                int d = n0 + nf * 8 + tid * 2;
                float2 r;
                r.x = acc[mf][nf][h * 2 + 0] + g_c[b * DD + d];
                r.y = acc[mf][nf][h * 2 + 1] + g_c[b * DD + d + 1];
                *(float2*)&out[ob + d] = r;
            }
        }
}

// ---------------- launch ---------------------------------------------------
extern "C" void kernel_launch(void* const* d_in, const int* in_sizes, int n_in,
                              void* d_out, int out_size) {
    const int*   ci = (const int*)d_in[0];
    const float* qv = (const float*)d_in[1];   // cas_embs = Q = V
    const void*  mk = d_in[2];
    const float* te = (const float*)d_in[3];
    float* out = (float*)d_out;

    cudaFuncSetAttribute(ta_gemm1, cudaFuncAttributeMaxDynamicSharedMemorySize, SMEM_BYTES);
    cudaFuncSetAttribute(ta_gemm2, cudaFuncAttributeMaxDynamicSharedMemorySize, SMEM_BYTES);

    ta_detect<<<1, 256>>>((const unsigned int*)mk);
    ta_buildmask<<<(BB * LS) / 256, 256>>>(mk);
    ta_qtflag<<<dim3(16, BB), 128>>>();
    ta_prep<<<(BB * LS * DD) / 256, 256>>>(ci, qv, te);
    ta_gemm1<<<dim3(136, BB), 256, SMEM_BYTES>>>();
    ta_dred<<<dim3(16, BB), 128>>>();
    ta_cpart<<<dim3(16, BB), 128>>>(qv);
    ta_cfin<<<BB, 128>>>();
    ta_vt<<<dim3(LS / 32, DD / 32, BB), dim3(32, 8)>>>(qv);
    ta_gemm2<<<dim3(16, BB), 256, SMEM_BYTES>>>(out);
}

// round 5
// speedup vs baseline: 3.9812x; 1.4090x over previous
#include <cuda_runtime.h>
#include <cuda_fp16.h>
#include <math.h>
#include <stdint.h>

#define BB 16
#define LS 2048
#define DD 128

// ---------------- scratch (device globals; no allocations) ----------------
__device__ __half g_Ph[(size_t)BB * LS * LS];          // P fp16 (134MB)
__device__ __half g_Qh[(size_t)BB * LS * DD];
__device__ __half g_Ql[(size_t)BB * LS * DD];
__device__ __half g_Kh[(size_t)BB * LS * DD];
__device__ __half g_Kl[(size_t)BB * LS * DD];
__device__ __half g_Vth[(size_t)BB * DD * LS];         // inv[k]*V transposed, hi
__device__ __half g_Vtl[(size_t)BB * DD * LS];         // lo
__device__ float g_dpart[BB * 16 * LS];                // per-(b,qt) column partials
__device__ float g_inv[BB * LS];
__device__ float g_cpart[BB * 16 * DD];
__device__ float g_c[BB * DD];
__device__ unsigned char g_m[BB * LS];
__device__ int g_qtflag[BB * 16];                      // 1 = whole q-tile masked
__device__ int g_maskmode;

// gemm1 smem: 4 fp16 tiles 128x64 pitch-144B = 18432B each
#define T_AH 0
#define T_AL 18432
#define T_BH 36864
#define T_BL 55296
#define G1_SMEM 74752
#define RED_OFF 73728           // 2x128 floats
// gemm2 smem: 2 stages x (P 18432 + Vh 18432 + Vl 18432) = 110592
#define G2_STG 55296
#define G2_SMEM 110592

// ---------------- helpers ---------------------------------------------------
__device__ __forceinline__ uint32_t smem_u32(const void* p) {
    uint32_t a;
    asm("{ .reg .u64 t; cvta.to.shared.u64 t, %1; cvt.u32.u64 %0, t; }" : "=r"(a) : "l"(p));
    return a;
}
__device__ __forceinline__ void ldsm4(uint32_t& r0, uint32_t& r1, uint32_t& r2,
                                      uint32_t& r3, uint32_t addr) {
    asm volatile("ldmatrix.sync.aligned.m8n8.x4.shared.b16 {%0,%1,%2,%3}, [%4];"
                 : "=r"(r0), "=r"(r1), "=r"(r2), "=r"(r3) : "r"(addr));
}
__device__ __forceinline__ void mma16816(float* c, const uint32_t* a, const uint32_t* b) {
    asm volatile("mma.sync.aligned.m16n8k16.row.col.f32.f16.f16.f32 "
                 "{%0,%1,%2,%3},{%4,%5,%6,%7},{%8,%9},{%0,%1,%2,%3};"
                 : "+f"(c[0]), "+f"(c[1]), "+f"(c[2]), "+f"(c[3])
                 : "r"(a[0]), "r"(a[1]), "r"(a[2]), "r"(a[3]), "r"(b[0]), "r"(b[1]));
}
#define CP_COMMIT() asm volatile("cp.async.commit_group;" ::: "memory")
#define CP_WAIT(n)  asm volatile("cp.async.wait_group %0;" :: "n"(n) : "memory")

// synchronous tile load: 128 rows x 64 cols fp16 -> smem pitch 144B
__device__ __forceinline__ void load_tile(const __half* __restrict__ g,
                                          size_t rowstride, char* st, int t) {
    #pragma unroll
    for (int it = 0; it < 4; it++) {
        int idx = it * 256 + t;
        int r = idx >> 3, gp = idx & 7;
        uint4 v = *(const uint4*)(g + (size_t)r * rowstride + gp * 8);
        *(uint4*)(st + r * 144 + gp * 16) = v;
    }
}
// async version (cp.async.cg 16B)
__device__ __forceinline__ void load_tile_async(const __half* __restrict__ g,
                                                size_t rowstride, char* st, int t) {
    uint32_t sa = smem_u32(st);
    #pragma unroll
    for (int it = 0; it < 4; it++) {
        int idx = it * 256 + t;
        int r = idx >> 3, gp = idx & 7;
        asm volatile("cp.async.cg.shared.global [%0], [%1], 16;"
                     :: "r"(sa + r * 144 + gp * 16),
                        "l"(g + (size_t)r * rowstride + gp * 8) : "memory");
    }
}

// one mma pass (A 128x64 x B^T 128x64, k=64) from smem tiles
__device__ __forceinline__ void mma_pass(char* pA, char* pB, int lane, int m0, int n0,
                                         float acc[2][8][4]) {
    int arow = (lane & 7) + ((lane >> 3) & 1) * 8;
    int acol = ((lane >> 4) & 1) * 8;
    int brow = (lane & 7) + ((lane >> 4) & 1) * 8;
    int bcol = ((lane >> 3) & 1) * 8;
    #pragma unroll
    for (int ks = 0; ks < 4; ks++) {
        int k0 = ks * 16;
        uint32_t a[8], bfr[16];
        #pragma unroll
        for (int mf = 0; mf < 2; mf++)
            ldsm4(a[mf*4], a[mf*4+1], a[mf*4+2], a[mf*4+3],
                  smem_u32(pA + (m0 + mf*16 + arow) * 144 + (k0 + acol) * 2));
        #pragma unroll
        for (int bg = 0; bg < 4; bg++)
            ldsm4(bfr[bg*4], bfr[bg*4+1], bfr[bg*4+2], bfr[bg*4+3],
                  smem_u32(pB + (n0 + bg*16 + brow) * 144 + (k0 + bcol) * 2));
        #pragma unroll
        for (int mf = 0; mf < 2; mf++)
            #pragma unroll
            for (int nf = 0; nf < 8; nf++)
                mma16816(acc[mf][nf], &a[mf*4], &bfr[(nf >> 1) * 4 + (nf & 1) * 2]);
    }
}

// ---------------- small kernels --------------------------------------------
__global__ void ta_detect(const unsigned int* m) {
    __shared__ int sF, sB;
    if (threadIdx.x == 0) { sF = 0; sB = 0; }
    __syncthreads();
    int f = 0, bg = 0;
    for (int i = threadIdx.x; i < (BB * LS) / 4; i += blockDim.x) {
        unsigned v = m[i];
        if (v == 0x3F800000u) f = 1; else if (v > 1u) bg = 1;
    }
    if (f) atomicOr(&sF, 1);
    if (bg) atomicOr(&sB, 1);
    __syncthreads();
    if (threadIdx.x == 0) g_maskmode = sF ? 2 : (sB ? 1 : 0);
}

// build clean mask + per-128-row-tile all-masked flags (block = 2 tiles)
__global__ void ta_buildmask(const void* mraw) {
    int t = threadIdx.x;
    int i = blockIdx.x * 256 + t;
    int mode = g_maskmode;
    unsigned char v = (mode == 1) ? (((const unsigned char*)mraw)[i] ? 1 : 0)
                                  : (((const unsigned int*)mraw)[i] ? 1 : 0);
    g_m[i] = v;
    __shared__ int cnt[2];
    if (t < 2) cnt[t] = 0;
    __syncthreads();
    if (!v) atomicAdd(&cnt[t >> 7], 1);
    __syncthreads();
    if (t < 2) g_qtflag[blockIdx.x * 2 + t] = (cnt[t] == 0);
}

__global__ void ta_prep(const int* __restrict__ ci, const float* __restrict__ Q,
                        const float* __restrict__ te) {
    int i = blockIdx.x * blockDim.x + threadIdx.x;   // over BB*LS*DD
    int row = i >> 7, c = i & 127;
    float q = Q[i];
    __half qh = __float2half_rn(q);
    g_Qh[i] = qh; g_Ql[i] = __float2half_rn(q - __half2float(qh));
    float k = te[ci[row] * DD + c];
    __half kh = __float2half_rn(k);
    g_Kh[i] = kh; g_Kl[i] = __float2half_rn(k - __half2float(kh));
}

__global__ void ta_dred() {
    int b = blockIdx.y, kt = blockIdx.x, t = threadIdx.x;
    int k = kt * 128 + t;
    float s = 0.f;
    for (int qt = kt; qt < 16; qt++) s += g_dpart[(b * 16 + qt) * LS + k];
    g_inv[b * LS + k] = (s != 0.f) ? 1.f / s : 0.f;
}

__global__ void ta_cpart(const float* __restrict__ V) {
    int b = blockIdx.y, ch = blockIdx.x, t = threadIdx.x;
    float s = 0.f;
    for (int k2 = 0; k2 < 128; k2++) {
        int k = ch * 128 + k2;
        if (g_inv[b * LS + k] == 0.f) s += V[((size_t)(b * LS + k)) * DD + t];
    }
    g_cpart[(b * 16 + ch) * DD + t] = s;
}

__global__ void ta_cfin() {
    int b = blockIdx.x, t = threadIdx.x;
    float s = 0.f;
    for (int ch = 0; ch < 16; ch++) s += g_cpart[(b * 16 + ch) * DD + t];
    g_c[b * DD + t] = s * (1.0f / (float)LS);
}

__global__ void ta_vt(const float* __restrict__ V) {
    __shared__ float sm[32][33];
    int b = blockIdx.z, k0 = blockIdx.x * 32, d0 = blockIdx.y * 32;
    int tx = threadIdx.x, ty = threadIdx.y;    // 32 x 8
    #pragma unroll
    for (int i = 0; i < 4; i++) {
        int kk = ty + i * 8;
        sm[kk][tx] = V[((size_t)(b * LS + k0 + kk)) * DD + d0 + tx];
    }
    __syncthreads();
    #pragma unroll
    for (int i = 0; i < 4; i++) {
        int dd_ = ty + i * 8;
        int k = k0 + tx;
        float v = sm[tx][dd_] * g_inv[b * LS + k];
        __half h = __float2half_rn(v);
        __half l = __float2half_rn(v - __half2float(h));
        size_t o = ((size_t)(b * DD + d0 + dd_)) * LS + k;
        g_Vth[o] = h; g_Vtl[o] = l;
    }
}

// ---------------- GEMM1: S = Q.K^T, exp, colsum, P store -------------------
__global__ void __launch_bounds__(256, 2) ta_gemm1() {
    int x = blockIdx.x, b = blockIdx.y;
    int qt = (int)((sqrtf(8.f * x + 1.f) - 1.f) * 0.5f);
    while ((qt + 1) * (qt + 2) / 2 <= x) qt++;
    while (qt * (qt + 1) / 2 > x) qt--;
    int kt = x - qt * (qt + 1) / 2;
    int qb = qt << 7, kb = kt << 7;
    int t = threadIdx.x, lane = t & 31, wid = t >> 5;

    if (g_qtflag[b * 16 + qt]) {               // whole q-tile masked: P never read
        if (t < 128) g_dpart[(b * 16 + qt) * LS + kb + t] = 0.f;
        return;
    }

    extern __shared__ char smem[];
    int m0 = (wid & 3) * 32, n0 = (wid >> 2) * 64;
    float acc[2][8][4];
    #pragma unroll
    for (int i = 0; i < 2; i++)
        #pragma unroll
        for (int j = 0; j < 8; j++)
            #pragma unroll
            for (int v = 0; v < 4; v++) acc[i][j][v] = 0.f;

    const __half* Qh = g_Qh + ((size_t)(b * LS + qb)) * DD;
    const __half* Ql = g_Ql + ((size_t)(b * LS + qb)) * DD;
    const __half* Kh = g_Kh + ((size_t)(b * LS + kb)) * DD;
    const __half* Kl = g_Kl + ((size_t)(b * LS + kb)) * DD;

    for (int ic = 0; ic < 2; ic++) {
        int kc = ic * 64;
        __syncthreads();
        load_tile(Qh + kc, DD, smem + T_AH, t);
        load_tile(Ql + kc, DD, smem + T_AL, t);
        load_tile(Kh + kc, DD, smem + T_BH, t);
        load_tile(Kl + kc, DD, smem + T_BL, t);
        __syncthreads();
        mma_pass(smem + T_AH, smem + T_BH, lane, m0, n0, acc);
        mma_pass(smem + T_AH, smem + T_BL, lane, m0, n0, acc);
        mma_pass(smem + T_AL, smem + T_BH, lane, m0, n0, acc);
    }
    __syncthreads();

    // epilogue: mask + exp -> staged fp32 tile [128][132]
    float* ep = (float*)smem;
    int gid = lane >> 2, tid = lane & 3;
    const float invt = 1.0f / (sqrtf((float)DD) + 1e-6f);
    #pragma unroll
    for (int mf = 0; mf < 2; mf++)
        #pragma unroll
        for (int h = 0; h < 2; h++) {
            int m = m0 + mf * 16 + h * 8 + gid;
            int gq = qb + m;
            int pm = g_m[b * LS + gq];
            #pragma unroll
            for (int nf = 0; nf < 8; nf++) {
                int n = n0 + nf * 8 + tid * 2;
                int gk = kb + n;
                float v0 = acc[mf][nf][h * 2 + 0];
                float v1 = acc[mf][nf][h * 2 + 1];
                ep[m * 132 + n]     = (pm || gk > gq)     ? 0.f : __expf(v0 * invt);
                ep[m * 132 + n + 1] = (pm || gk + 1 > gq) ? 0.f : __expf(v1 * invt);
            }
        }
    __syncthreads();

    // deterministic column sums (split 2x over rows)
    int col = t & 127, hf = t >> 7;
    float s = 0.f;
    #pragma unroll 8
    for (int r = 0; r < 64; r++) s += ep[(hf * 64 + r) * 132 + col];
    float* red = (float*)(smem + RED_OFF);
    red[hf * 128 + col] = s;
    __syncthreads();
    if (t < 128) g_dpart[(b * 16 + qt) * LS + kb + t] = red[t] + red[128 + t];

    // P store: fp16 (hi only), coalesced 4B
    #pragma unroll
    for (int it = 0; it < 32; it++) {
        int idx = it * 256 + t;
        int r = idx >> 6, c0 = (idx & 63) * 2;
        __half2 hp;
        hp.x = __float2half_rn(ep[r * 132 + c0]);
        hp.y = __float2half_rn(ep[r * 132 + c0 + 1]);
        *(__half2*)&g_Ph[((size_t)(b * LS + qb + r)) * LS + kb + c0] = hp;
    }
}

// ---------------- GEMM2: out = P . (inv*V)^T + c, cp.async pipelined -------
__global__ void __launch_bounds__(256, 2) ta_gemm2(float* __restrict__ out) {
    int qt = 15 - blockIdx.x, b = blockIdx.y;
    int qb = qt << 7;
    int t = threadIdx.x, lane = t & 31, wid = t >> 5;

    if (g_qtflag[b * 16 + qt]) {               // out rows = c
        if (t < 128) {
            float cv = g_c[b * DD + t];
            for (int r = 0; r < 128; r++)
                out[((size_t)(b * LS + qb + r)) * DD + t] = cv;
        }
        return;
    }

    extern __shared__ char smem[];
    int m0 = (wid & 3) * 32, n0 = (wid >> 2) * 64;
    float acc[2][8][4];
    #pragma unroll
    for (int i = 0; i < 2; i++)
        #pragma unroll
        for (int j = 0; j < 8; j++)
            #pragma unroll
            for (int v = 0; v < 4; v++) acc[i][j][v] = 0.f;

    const __half* Ph = g_Ph + ((size_t)(b * LS + qb)) * LS;
    const __half* Vh = g_Vth + (size_t)b * DD * LS;
    const __half* Vl = g_Vtl + (size_t)b * DD * LS;

    int nck = (qt + 1) * 2;
    // prologue: stage 0
    load_tile_async(Ph, LS, smem + 0, t);
    load_tile_async(Vh, LS, smem + 18432, t);
    load_tile_async(Vl, LS, smem + 36864, t);
    CP_COMMIT();

    for (int ic = 0; ic < nck; ic++) {
        char* st = smem + (ic & 1) * G2_STG;
        if (ic + 1 < nck) {
            char* st2 = smem + ((ic + 1) & 1) * G2_STG;
            int kc2 = (ic + 1) * 64;
            load_tile_async(Ph + kc2, LS, st2 + 0, t);
            load_tile_async(Vh + kc2, LS, st2 + 18432, t);
            load_tile_async(Vl + kc2, LS, st2 + 36864, t);
            CP_COMMIT();
            CP_WAIT(1);
        } else {
            CP_WAIT(0);
        }
        __syncthreads();
        mma_pass(st + 0, st + 18432, lane, m0, n0, acc);
        mma_pass(st + 0, st + 36864, lane, m0, n0, acc);
        __syncthreads();
    }

    int gid = lane >> 2, tid = lane & 3;
    #pragma unroll
    for (int mf = 0; mf < 2; mf++)
        #pragma unroll
        for (int h = 0; h < 2; h++) {
            int m = m0 + mf * 16 + h * 8 + gid;
            size_t ob = ((size_t)(b * LS + qb + m)) * DD;
            #pragma unroll
            for (int nf = 0; nf < 8; nf++) {
                int d = n0 + nf * 8 + tid * 2;
                float2 r;
                r.x = acc[mf][nf][h * 2 + 0] + g_c[b * DD + d];
                r.y = acc[mf][nf][h * 2 + 1] + g_c[b * DD + d + 1];
                *(float2*)&out[ob + d] = r;
            }
        }
}

// ---------------- launch ---------------------------------------------------
extern "C" void kernel_launch(void* const* d_in, const int* in_sizes, int n_in,
                              void* d_out, int out_size) {
    const int*   ci = (const int*)d_in[0];
    const float* qv = (const float*)d_in[1];   // cas_embs = Q = V
    const void*  mk = d_in[2];
    const float* te = (const float*)d_in[3];
    float* out = (float*)d_out;

    cudaFuncSetAttribute(ta_gemm1, cudaFuncAttributeMaxDynamicSharedMemorySize, G1_SMEM);
    cudaFuncSetAttribute(ta_gemm2, cudaFuncAttributeMaxDynamicSharedMemorySize, G2_SMEM);

    ta_detect<<<1, 256>>>((const unsigned int*)mk);
    ta_buildmask<<<(BB * LS) / 256, 256>>>(mk);
    ta_prep<<<(BB * LS * DD) / 256, 256>>>(ci, qv, te);
    ta_gemm1<<<dim3(136, BB), 256, G1_SMEM>>>();
    ta_dred<<<dim3(16, BB), 128>>>();
    ta_cpart<<<dim3(16, BB), 128>>>(qv);
    ta_cfin<<<BB, 128>>>();
    ta_vt<<<dim3(LS / 32, DD / 32, BB), dim3(32, 8)>>>(qv);
    ta_gemm2<<<dim3(16, BB), 256, G2_SMEM>>>(out);
}

// round 6
// speedup vs baseline: 4.6455x; 1.1669x over previous
#include <cuda_runtime.h>
#include <cuda_fp16.h>
#include <math.h>
#include <stdint.h>

#define BB 16
#define LS 2048
#define DD 128

// ---------------- scratch (device globals; no allocations) ----------------
__device__ __half g_Ph[(size_t)BB * LS * LS];          // P fp16 (134MB)
__device__ __half g_Qh[(size_t)BB * LS * DD];
__device__ __half g_Kh[(size_t)BB * LS * DD];
__device__ __half g_Vth[(size_t)BB * DD * LS];         // inv[k]*V transposed fp16
__device__ float g_dpart[BB * 16 * LS];                // per-(b,qt) column partials
__device__ float g_inv[BB * LS];
__device__ float g_cpart[BB * 16 * DD];
__device__ float g_c[BB * DD];
__device__ unsigned char g_m[BB * LS];
__device__ int g_qtflag[BB * 16];                      // 1 = whole q-tile masked
__device__ int g_maskmode;

// gemm1 smem: Q tile 18432 + K tile 18432 = 36864; epilogue reuses:
//   half ep[128][132] = 33792B, red floats at 33792 (1024B)
#define G1_TB 18432
#define G1_SMEM 36864
#define RED_OFF 33792
// gemm2 smem: 2 stages x (P 128x64 tile 18432 + V 64x64 tile 9216) = 55296
#define G2_PV 27648
#define G2_SMEM 55296

// ---------------- helpers ---------------------------------------------------
__device__ __forceinline__ uint32_t smem_u32(const void* p) {
    uint32_t a;
    asm("{ .reg .u64 t; cvta.to.shared.u64 t, %1; cvt.u32.u64 %0, t; }" : "=r"(a) : "l"(p));
    return a;
}
__device__ __forceinline__ void ldsm4(uint32_t& r0, uint32_t& r1, uint32_t& r2,
                                      uint32_t& r3, uint32_t addr) {
    asm volatile("ldmatrix.sync.aligned.m8n8.x4.shared.b16 {%0,%1,%2,%3}, [%4];"
                 : "=r"(r0), "=r"(r1), "=r"(r2), "=r"(r3) : "r"(addr));
}
__device__ __forceinline__ void mma16816(float* c, const uint32_t* a, const uint32_t* b) {
    asm volatile("mma.sync.aligned.m16n8k16.row.col.f32.f16.f16.f32 "
                 "{%0,%1,%2,%3},{%4,%5,%6,%7},{%8,%9},{%0,%1,%2,%3};"
                 : "+f"(c[0]), "+f"(c[1]), "+f"(c[2]), "+f"(c[3])
                 : "r"(a[0]), "r"(a[1]), "r"(a[2]), "r"(a[3]), "r"(b[0]), "r"(b[1]));
}
#define CP_COMMIT() asm volatile("cp.async.commit_group;" ::: "memory")
#define CP_WAIT(n)  asm volatile("cp.async.wait_group %0;" :: "n"(n) : "memory")

// tile load: ROWS x 64 fp16 -> smem pitch 144B
template <int ROWS>
__device__ __forceinline__ void load_tile(const __half* __restrict__ g,
                                          size_t rowstride, char* st, int t) {
    #pragma unroll
    for (int it = 0; it < ROWS / 32; it++) {
        int idx = it * 256 + t;
        int r = idx >> 3, gp = idx & 7;
        uint4 v = *(const uint4*)(g + (size_t)r * rowstride + gp * 8);
        *(uint4*)(st + r * 144 + gp * 16) = v;
    }
}
template <int ROWS>
__device__ __forceinline__ void load_tile_async(const __half* __restrict__ g,
                                                size_t rowstride, char* st, int t) {
    uint32_t sa = smem_u32(st);
    #pragma unroll
    for (int it = 0; it < ROWS / 32; it++) {
        int idx = it * 256 + t;
        int r = idx >> 3, gp = idx & 7;
        asm volatile("cp.async.cg.shared.global [%0], [%1], 16;"
                     :: "r"(sa + r * 144 + gp * 16),
                        "l"(g + (size_t)r * rowstride + gp * 8) : "memory");
    }
}

// one mma pass, A 32x64 warp-tile x B^T (NG*32)x64, k=64
template <int NG>
__device__ __forceinline__ void mma_pass(char* pA, char* pB, int lane, int m0, int n0,
                                         float acc[2][2 * NG][4]) {
    int arow = (lane & 7) + ((lane >> 3) & 1) * 8;
    int acol = ((lane >> 4) & 1) * 8;
    int brow = (lane & 7) + ((lane >> 4) & 1) * 8;
    int bcol = ((lane >> 3) & 1) * 8;
    #pragma unroll
    for (int ks = 0; ks < 4; ks++) {
        int k0 = ks * 16;
        uint32_t a[8], bfr[4 * NG];
        #pragma unroll
        for (int mf = 0; mf < 2; mf++)
            ldsm4(a[mf*4], a[mf*4+1], a[mf*4+2], a[mf*4+3],
                  smem_u32(pA + (m0 + mf*16 + arow) * 144 + (k0 + acol) * 2));
        #pragma unroll
        for (int bg = 0; bg < NG; bg++)
            ldsm4(bfr[bg*4], bfr[bg*4+1], bfr[bg*4+2], bfr[bg*4+3],
                  smem_u32(pB + (n0 + bg*16 + brow) * 144 + (k0 + bcol) * 2));
        #pragma unroll
        for (int mf = 0; mf < 2; mf++)
            #pragma unroll
            for (int nf = 0; nf < 2 * NG; nf++)
                mma16816(acc[mf][nf], &a[mf*4], &bfr[(nf >> 1) * 4 + (nf & 1) * 2]);
    }
}

// ---------------- small kernels --------------------------------------------
__global__ void ta_detect(const unsigned int* m) {
    __shared__ int sF, sB;
    if (threadIdx.x == 0) { sF = 0; sB = 0; }
    __syncthreads();
    int f = 0, bg = 0;
    for (int i = threadIdx.x; i < (BB * LS) / 4; i += blockDim.x) {
        unsigned v = m[i];
        if (v == 0x3F800000u) f = 1; else if (v > 1u) bg = 1;
    }
    if (f) atomicOr(&sF, 1);
    if (bg) atomicOr(&sB, 1);
    __syncthreads();
    if (threadIdx.x == 0) g_maskmode = sF ? 2 : (sB ? 1 : 0);
}

__global__ void ta_buildmask(const void* mraw) {
    int t = threadIdx.x;
    int i = blockIdx.x * 256 + t;
    int mode = g_maskmode;
    unsigned char v = (mode == 1) ? (((const unsigned char*)mraw)[i] ? 1 : 0)
                                  : (((const unsigned int*)mraw)[i] ? 1 : 0);
    g_m[i] = v;
    __shared__ int cnt[2];
    if (t < 2) cnt[t] = 0;
    __syncthreads();
    if (!v) atomicAdd(&cnt[t >> 7], 1);
    __syncthreads();
    if (t < 2) g_qtflag[blockIdx.x * 2 + t] = (cnt[t] == 0);
}

__global__ void ta_prep(const int* __restrict__ ci, const float* __restrict__ Q,
                        const float* __restrict__ te) {
    int i = blockIdx.x * blockDim.x + threadIdx.x;   // over BB*LS*DD
    int row = i >> 7, c = i & 127;
    g_Qh[i] = __float2half_rn(Q[i]);
    g_Kh[i] = __float2half_rn(te[ci[row] * DD + c]);
}

__global__ void ta_dred() {
    int b = blockIdx.y, kt = blockIdx.x, t = threadIdx.x;
    int k = kt * 128 + t;
    float s = 0.f;
    for (int qt = kt; qt < 16; qt++) s += g_dpart[(b * 16 + qt) * LS + k];
    g_inv[b * LS + k] = (s != 0.f) ? 1.f / s : 0.f;
}

__global__ void ta_cpart(const float* __restrict__ V) {
    int b = blockIdx.y, ch = blockIdx.x, t = threadIdx.x;
    float s = 0.f;
    for (int k2 = 0; k2 < 128; k2++) {
        int k = ch * 128 + k2;
        if (g_inv[b * LS + k] == 0.f) s += V[((size_t)(b * LS + k)) * DD + t];
    }
    g_cpart[(b * 16 + ch) * DD + t] = s;
}

__global__ void ta_cfin() {
    int b = blockIdx.x, t = threadIdx.x;
    float s = 0.f;
    for (int ch = 0; ch < 16; ch++) s += g_cpart[(b * 16 + ch) * DD + t];
    g_c[b * DD + t] = s * (1.0f / (float)LS);
}

__global__ void ta_vt(const float* __restrict__ V) {
    __shared__ float sm[32][33];
    int b = blockIdx.z, k0 = blockIdx.x * 32, d0 = blockIdx.y * 32;
    int tx = threadIdx.x, ty = threadIdx.y;    // 32 x 8
    #pragma unroll
    for (int i = 0; i < 4; i++) {
        int kk = ty + i * 8;
        sm[kk][tx] = V[((size_t)(b * LS + k0 + kk)) * DD + d0 + tx];
    }
    __syncthreads();
    #pragma unroll
    for (int i = 0; i < 4; i++) {
        int dd_ = ty + i * 8;
        int k = k0 + tx;
        float v = sm[tx][dd_] * g_inv[b * LS + k];
        g_Vth[((size_t)(b * DD + d0 + dd_)) * LS + k] = __float2half_rn(v);
    }
}

// ---------------- GEMM1: S = Q.K^T, exp, colsum, P store -------------------
__global__ void __launch_bounds__(256, 2) ta_gemm1() {
    int x = blockIdx.x, b = blockIdx.y;
    int qt = (int)((sqrtf(8.f * x + 1.f) - 1.f) * 0.5f);
    while ((qt + 1) * (qt + 2) / 2 <= x) qt++;
    while (qt * (qt + 1) / 2 > x) qt--;
    int kt = x - qt * (qt + 1) / 2;
    int qb = qt << 7, kb = kt << 7;
    int t = threadIdx.x, lane = t & 31, wid = t >> 5;

    if (g_qtflag[b * 16 + qt]) {               // whole q-tile masked: P never read
        if (t < 128) g_dpart[(b * 16 + qt) * LS + kb + t] = 0.f;
        return;
    }

    extern __shared__ char smem[];
    int m0 = (wid & 3) * 32, n0 = (wid >> 2) * 64;
    float acc[2][8][4];
    #pragma unroll
    for (int i = 0; i < 2; i++)
        #pragma unroll
        for (int j = 0; j < 8; j++)
            #pragma unroll
            for (int v = 0; v < 4; v++) acc[i][j][v] = 0.f;

    const __half* Qh = g_Qh + ((size_t)(b * LS + qb)) * DD;
    const __half* Kh = g_Kh + ((size_t)(b * LS + kb)) * DD;

    #pragma unroll
    for (int ic = 0; ic < 2; ic++) {
        int kc = ic * 64;
        __syncthreads();
        load_tile<128>(Qh + kc, DD, smem, t);
        load_tile<128>(Kh + kc, DD, smem + G1_TB, t);
        __syncthreads();
        mma_pass<4>(smem, smem + G1_TB, lane, m0, n0, acc);
    }
    __syncthreads();

    // epilogue: mask + exp -> staged fp16 tile [128][132]
    __half* ep = (__half*)smem;
    int gid = lane >> 2, tid = lane & 3;
    const float invt = 1.0f / (sqrtf((float)DD) + 1e-6f);
    #pragma unroll
    for (int mf = 0; mf < 2; mf++)
        #pragma unroll
        for (int h = 0; h < 2; h++) {
            int m = m0 + mf * 16 + h * 8 + gid;
            int gq = qb + m;
            int pm = g_m[b * LS + gq];
            #pragma unroll
            for (int nf = 0; nf < 8; nf++) {
                int n = n0 + nf * 8 + tid * 2;
                int gk = kb + n;
                float v0 = acc[mf][nf][h * 2 + 0];
                float v1 = acc[mf][nf][h * 2 + 1];
                __half2 hp;
                hp.x = (pm || gk > gq)     ? __half(0.f) : __float2half_rn(__expf(v0 * invt));
                hp.y = (pm || gk + 1 > gq) ? __half(0.f) : __float2half_rn(__expf(v1 * invt));
                *(__half2*)&ep[m * 132 + n] = hp;
            }
        }
    __syncthreads();

    // deterministic column sums over staged (rounded) P — consistent with store
    int col = t & 127, hf = t >> 7;
    float s = 0.f;
    #pragma unroll 8
    for (int r = 0; r < 64; r++) s += __half2float(ep[(hf * 64 + r) * 132 + col]);
    float* red = (float*)(smem + RED_OFF);
    red[hf * 128 + col] = s;
    __syncthreads();
    if (t < 128) g_dpart[(b * 16 + qt) * LS + kb + t] = red[t] + red[128 + t];

    // P store: 8B groups, coalesced
    #pragma unroll
    for (int it = 0; it < 16; it++) {
        int idx = it * 256 + t;
        int r = idx >> 5, g4 = (idx & 31) * 4;       // 32 groups of 4 halfs per row
        uint2 v = *(uint2*)&ep[r * 132 + g4];
        *(uint2*)&g_Ph[((size_t)(b * LS + qb + r)) * LS + kb + g4] = v;
    }
}

// ---------------- GEMM2: out = P . (inv*V)^T + c, pipelined, d-split -------
__global__ void __launch_bounds__(256, 3) ta_gemm2(float* __restrict__ out) {
    int qt = 15 - (blockIdx.x >> 1), dh = blockIdx.x & 1, b = blockIdx.y;
    int qb = qt << 7, db = dh << 6;
    int t = threadIdx.x, lane = t & 31, wid = t >> 5;

    if (g_qtflag[b * 16 + qt]) {               // out rows = c
        #pragma unroll
        for (int it = 0; it < 32; it++) {
            int idx = it * 256 + t;
            int r = idx >> 6, c = idx & 63;
            out[((size_t)(b * LS + qb + r)) * DD + db + c] = g_c[b * DD + db + c];
        }
        return;
    }

    extern __shared__ char smem[];
    int m0 = (wid & 3) * 32, n0 = (wid >> 2) * 32;
    float acc[2][4][4];
    #pragma unroll
    for (int i = 0; i < 2; i++)
        #pragma unroll
        for (int j = 0; j < 4; j++)
            #pragma unroll
            for (int v = 0; v < 4; v++) acc[i][j][v] = 0.f;

    const __half* Ph = g_Ph + ((size_t)(b * LS + qb)) * LS;
    const __half* Vh = g_Vth + ((size_t)(b * DD + db)) * LS;

    int nck = (qt + 1) * 2;
    load_tile_async<128>(Ph, LS, smem, t);
    load_tile_async<64>(Vh, LS, smem + G1_TB, t);
    CP_COMMIT();

    for (int ic = 0; ic < nck; ic++) {
        char* st = smem + (ic & 1) * G2_PV;
        if (ic + 1 < nck) {
            char* st2 = smem + ((ic + 1) & 1) * G2_PV;
            int kc2 = (ic + 1) * 64;
            load_tile_async<128>(Ph + kc2, LS, st2, t);
            load_tile_async<64>(Vh + kc2, LS, st2 + G1_TB, t);
            CP_COMMIT();
            CP_WAIT(1);
        } else {
            CP_WAIT(0);
        }
        __syncthreads();
        mma_pass<2>(st, st + G1_TB, lane, m0, n0, acc);
        __syncthreads();
    }

    int gid = lane >> 2, tid = lane & 3;
    #pragma unroll
    for (int mf = 0; mf < 2; mf++)
        #pragma unroll
        for (int h = 0; h < 2; h++) {
            int m = m0 + mf * 16 + h * 8 + gid;
            size_t ob = ((size_t)(b * LS + qb + m)) * DD;
            #pragma unroll
            for (int nf = 0; nf < 4; nf++) {
                int d = db + n0 + nf * 8 + tid * 2;
                float2 r;
                r.x = acc[mf][nf][h * 2 + 0] + g_c[b * DD + d];
                r.y = acc[mf][nf][h * 2 + 1] + g_c[b * DD + d + 1];
                *(float2*)&out[ob + d] = r;
            }
        }
}

// ---------------- launch ---------------------------------------------------
extern "C" void kernel_launch(void* const* d_in, const int* in_sizes, int n_in,
                              void* d_out, int out_size) {
    const int*   ci = (const int*)d_in[0];
    const float* qv = (const float*)d_in[1];   // cas_embs = Q = V
    const void*  mk = d_in[2];
    const float* te = (const float*)d_in[3];
    float* out = (float*)d_out;

    cudaFuncSetAttribute(ta_gemm1, cudaFuncAttributeMaxDynamicSharedMemorySize, G1_SMEM);
    cudaFuncSetAttribute(ta_gemm2, cudaFuncAttributeMaxDynamicSharedMemorySize, G2_SMEM);

    ta_detect<<<1, 256>>>((const unsigned int*)mk);
    ta_buildmask<<<(BB * LS) / 256, 256>>>(mk);
    ta_prep<<<(BB * LS * DD) / 256, 256>>>(ci, qv, te);
    ta_gemm1<<<dim3(136, BB), 256, G1_SMEM>>>();
    ta_dred<<<dim3(16, BB), 128>>>();
    ta_cpart<<<dim3(16, BB), 128>>>(qv);
    ta_cfin<<<BB, 128>>>();
    ta_vt<<<dim3(LS / 32, DD / 32, BB), dim3(32, 8)>>>(qv);
    ta_gemm2<<<dim3(32, BB), 256, G2_SMEM>>>(out);
}

// round 7
// speedup vs baseline: 7.1441x; 1.5379x over previous
#include <cuda_runtime.h>
#include <cuda_fp16.h>
#include <math.h>
#include <stdint.h>

#define BB 16
#define LS 2048
#define DD 128

// ---------------- scratch (device globals; no allocations) ----------------
__device__ __half g_Ph[(size_t)BB * LS * LS];          // P fp16 (134MB)
__device__ __half g_Qh[(size_t)BB * LS * DD];
__device__ __half g_Kh[(size_t)BB * LS * DD];
__device__ __half g_Vth[(size_t)BB * DD * LS];         // inv[k]*V transposed fp16
__device__ float g_dpart[BB * 16 * LS];                // per-(b,qt) column partials
__device__ float g_inv[BB * LS];
__device__ float g_cpart[BB * 16 * DD];
__device__ float g_c[BB * DD];
__device__ unsigned char g_m[BB * LS];
__device__ int g_qtflag[BB * 16];                      // 1 = whole q-tile masked
__device__ int g_maskmode;

// gemm1 smem: 4 tiles (Q0,Q1,K0,K1) 128x64 pitch-144B = 18432B each
#define G1_TB 18432
#define G1_SMEM 73728
// gemm2 smem: 2 stages x (P 128x64 18432 + V 64x64 9216) = 55296
#define G2_PV 27648
#define G2_SMEM 55296

// ---------------- helpers ---------------------------------------------------
__device__ __forceinline__ uint32_t smem_u32(const void* p) {
    uint32_t a;
    asm("{ .reg .u64 t; cvta.to.shared.u64 t, %1; cvt.u32.u64 %0, t; }" : "=r"(a) : "l"(p));
    return a;
}
__device__ __forceinline__ void ldsm4(uint32_t& r0, uint32_t& r1, uint32_t& r2,
                                      uint32_t& r3, uint32_t addr) {
    asm volatile("ldmatrix.sync.aligned.m8n8.x4.shared.b16 {%0,%1,%2,%3}, [%4];"
                 : "=r"(r0), "=r"(r1), "=r"(r2), "=r"(r3) : "r"(addr));
}
__device__ __forceinline__ void mma16816(float* c, const uint32_t* a, const uint32_t* b) {
    asm volatile("mma.sync.aligned.m16n8k16.row.col.f32.f16.f16.f32 "
                 "{%0,%1,%2,%3},{%4,%5,%6,%7},{%8,%9},{%0,%1,%2,%3};"
                 : "+f"(c[0]), "+f"(c[1]), "+f"(c[2]), "+f"(c[3])
                 : "r"(a[0]), "r"(a[1]), "r"(a[2]), "r"(a[3]), "r"(b[0]), "r"(b[1]));
}
#define CP_COMMIT() asm volatile("cp.async.commit_group;" ::: "memory")
#define CP_WAIT(n)  asm volatile("cp.async.wait_group %0;" :: "n"(n) : "memory")

template <int ROWS>
__device__ __forceinline__ void load_tile_async(const __half* __restrict__ g,
                                                size_t rowstride, char* st, int t) {
    uint32_t sa = smem_u32(st);
    #pragma unroll
    for (int it = 0; it < ROWS / 32; it++) {
        int idx = it * 256 + t;
        int r = idx >> 3, gp = idx & 7;
        asm volatile("cp.async.cg.shared.global [%0], [%1], 16;"
                     :: "r"(sa + r * 144 + gp * 16),
                        "l"(g + (size_t)r * rowstride + gp * 8) : "memory");
    }
}

// one mma pass, A 32x64 warp-tile x B^T (NG*32)x64, k=64
template <int NG>
__device__ __forceinline__ void mma_pass(char* pA, char* pB, int lane, int m0, int n0,
                                         float acc[2][2 * NG][4]) {
    int arow = (lane & 7) + ((lane >> 3) & 1) * 8;
    int acol = ((lane >> 4) & 1) * 8;
    int brow = (lane & 7) + ((lane >> 4) & 1) * 8;
    int bcol = ((lane >> 3) & 1) * 8;
    #pragma unroll
    for (int ks = 0; ks < 4; ks++) {
        int k0 = ks * 16;
        uint32_t a[8], bfr[4 * NG];
        #pragma unroll
        for (int mf = 0; mf < 2; mf++)
            ldsm4(a[mf*4], a[mf*4+1], a[mf*4+2], a[mf*4+3],
                  smem_u32(pA + (m0 + mf*16 + arow) * 144 + (k0 + acol) * 2));
        #pragma unroll
        for (int bg = 0; bg < NG; bg++)
            ldsm4(bfr[bg*4], bfr[bg*4+1], bfr[bg*4+2], bfr[bg*4+3],
                  smem_u32(pB + (n0 + bg*16 + brow) * 144 + (k0 + bcol) * 2));
        #pragma unroll
        for (int mf = 0; mf < 2; mf++)
            #pragma unroll
            for (int nf = 0; nf < 2 * NG; nf++)
                mma16816(acc[mf][nf], &a[mf*4], &bfr[(nf >> 1) * 4 + (nf & 1) * 2]);
    }
}

// ---------------- small kernels --------------------------------------------
__global__ void ta_detect(const unsigned int* m) {
    __shared__ int sF, sB;
    if (threadIdx.x == 0) { sF = 0; sB = 0; }
    __syncthreads();
    int f = 0, bg = 0;
    for (int i = threadIdx.x; i < (BB * LS) / 4; i += blockDim.x) {
        unsigned v = m[i];
        if (v == 0x3F800000u) f = 1; else if (v > 1u) bg = 1;
    }
    if (f) atomicOr(&sF, 1);
    if (bg) atomicOr(&sB, 1);
    __syncthreads();
    if (threadIdx.x == 0) g_maskmode = sF ? 2 : (sB ? 1 : 0);
}

__global__ void ta_buildmask(const void* mraw) {
    int t = threadIdx.x;
    int i = blockIdx.x * 256 + t;
    int mode = g_maskmode;
    unsigned char v = (mode == 1) ? (((const unsigned char*)mraw)[i] ? 1 : 0)
                                  : (((const unsigned int*)mraw)[i] ? 1 : 0);
    g_m[i] = v;
    __shared__ int cnt[2];
    if (t < 2) cnt[t] = 0;
    __syncthreads();
    if (!v) atomicAdd(&cnt[t >> 7], 1);
    __syncthreads();
    if (t < 2) g_qtflag[blockIdx.x * 2 + t] = (cnt[t] == 0);
}

__global__ void ta_prep(const int* __restrict__ ci, const float* __restrict__ Q,
                        const float* __restrict__ te) {
    int i = blockIdx.x * blockDim.x + threadIdx.x;   // over BB*LS*DD
    int row = i >> 7, c = i & 127;
    g_Qh[i] = __float2half_rn(Q[i]);
    g_Kh[i] = __float2half_rn(te[ci[row] * DD + c]);
}

__global__ void ta_dred() {
    int b = blockIdx.y, kt = blockIdx.x, t = threadIdx.x;
    int k = kt * 128 + t;
    float s = 0.f;
    for (int qt = kt; qt < 16; qt++) s += g_dpart[(b * 16 + qt) * LS + k];
    g_inv[b * LS + k] = (s != 0.f) ? 1.f / s : 0.f;
}

__global__ void ta_cpart(const float* __restrict__ V) {
    int b = blockIdx.y, ch = blockIdx.x, t = threadIdx.x;
    float s = 0.f;
    for (int k2 = 0; k2 < 128; k2++) {
        int k = ch * 128 + k2;
        if (g_inv[b * LS + k] == 0.f) s += V[((size_t)(b * LS + k)) * DD + t];
    }
    g_cpart[(b * 16 + ch) * DD + t] = s;
}

__global__ void ta_cfin() {
    int b = blockIdx.x, t = threadIdx.x;
    float s = 0.f;
    for (int ch = 0; ch < 16; ch++) s += g_cpart[(b * 16 + ch) * DD + t];
    g_c[b * DD + t] = s * (1.0f / (float)LS);
}

__global__ void ta_vt(const float* __restrict__ V) {
    __shared__ float sm[32][33];
    int b = blockIdx.z, k0 = blockIdx.x * 32, d0 = blockIdx.y * 32;
    int tx = threadIdx.x, ty = threadIdx.y;    // 32 x 8
    #pragma unroll
    for (int i = 0; i < 4; i++) {
        int kk = ty + i * 8;
        sm[kk][tx] = V[((size_t)(b * LS + k0 + kk)) * DD + d0 + tx];
    }
    __syncthreads();
    #pragma unroll
    for (int i = 0; i < 4; i++) {
        int dd_ = ty + i * 8;
        int k = k0 + tx;
        float v = sm[tx][dd_] * g_inv[b * LS + k];
        g_Vth[((size_t)(b * DD + d0 + dd_)) * LS + k] = __float2half_rn(v);
    }
}

// ---------------- GEMM1: S = Q.K^T, exp, colsum, P store (reg epilogue) ----
__global__ void __launch_bounds__(256, 2) ta_gemm1() {
    int x = blockIdx.x, b = blockIdx.y;
    int qt = (int)((sqrtf(8.f * x + 1.f) - 1.f) * 0.5f);
    while ((qt + 1) * (qt + 2) / 2 <= x) qt++;
    while (qt * (qt + 1) / 2 > x) qt--;
    int kt = x - qt * (qt + 1) / 2;
    int qb = qt << 7, kb = kt << 7;
    int t = threadIdx.x, lane = t & 31, wid = t >> 5;

    if (g_qtflag[b * 16 + qt]) {               // whole q-tile masked: P never read
        if (t < 128) g_dpart[(b * 16 + qt) * LS + kb + t] = 0.f;
        return;
    }

    extern __shared__ char smem[];
    int m0 = (wid & 3) * 32, n0 = (wid >> 2) * 64;
    float acc[2][8][4];
    #pragma unroll
    for (int i = 0; i < 2; i++)
        #pragma unroll
        for (int j = 0; j < 8; j++)
            #pragma unroll
            for (int v = 0; v < 4; v++) acc[i][j][v] = 0.f;

    const __half* Qh = g_Qh + ((size_t)(b * LS + qb)) * DD;
    const __half* Kh = g_Kh + ((size_t)(b * LS + kb)) * DD;

    // async-load all 4 tiles (both k-chunks), one wait, two mma passes
    load_tile_async<128>(Qh,      DD, smem + 0 * G1_TB, t);
    load_tile_async<128>(Qh + 64, DD, smem + 1 * G1_TB, t);
    load_tile_async<128>(Kh,      DD, smem + 2 * G1_TB, t);
    load_tile_async<128>(Kh + 64, DD, smem + 3 * G1_TB, t);
    CP_COMMIT();
    CP_WAIT(0);
    __syncthreads();
    mma_pass<4>(smem + 0 * G1_TB, smem + 2 * G1_TB, lane, m0, n0, acc);
    mma_pass<4>(smem + 1 * G1_TB, smem + 3 * G1_TB, lane, m0, n0, acc);

    // register epilogue: mask + exp, direct P store, column partials in regs
    int gid = lane >> 2, tid = lane & 3;
    const float invt = 1.0f / (sqrtf((float)DD) + 1e-6f);
    float colp[16];
    #pragma unroll
    for (int i = 0; i < 16; i++) colp[i] = 0.f;

    #pragma unroll
    for (int mf = 0; mf < 2; mf++)
        #pragma unroll
        for (int h = 0; h < 2; h++) {
            int m = m0 + mf * 16 + h * 8 + gid;
            int gq = qb + m;
            int pm = g_m[b * LS + gq];
            size_t rowb = ((size_t)(b * LS + gq)) * LS + kb;
            #pragma unroll
            for (int nf = 0; nf < 8; nf++) {
                int n = n0 + nf * 8 + tid * 2;
                int gk = kb + n;
                float v0 = acc[mf][nf][h * 2 + 0];
                float v1 = acc[mf][nf][h * 2 + 1];
                __half2 hp;
                hp.x = (pm || gk > gq)     ? __half(0.f) : __float2half_rn(__expf(v0 * invt));
                hp.y = (pm || gk + 1 > gq) ? __half(0.f) : __float2half_rn(__expf(v1 * invt));
                *(__half2*)&g_Ph[rowb + n] = hp;
                colp[nf * 2 + 0] += __half2float(hp.x);
                colp[nf * 2 + 1] += __half2float(hp.y);
            }
        }

    // reduce column partials over gid lanes (same tid): xor 4, 8, 16
    #pragma unroll
    for (int i = 0; i < 16; i++) {
        colp[i] += __shfl_xor_sync(0xFFFFFFFFu, colp[i], 4);
        colp[i] += __shfl_xor_sync(0xFFFFFFFFu, colp[i], 8);
        colp[i] += __shfl_xor_sync(0xFFFFFFFFu, colp[i], 16);
    }
    __syncthreads();                           // mma smem reads done; reuse smem
    float* red = (float*)smem;                 // [4 mwarps][128 cols]
    if (lane < 4) {
        int mw = wid & 3, nh = wid >> 2;
        #pragma unroll
        for (int nf = 0; nf < 8; nf++) {
            red[mw * 128 + nh * 64 + nf * 8 + lane * 2 + 0] = colp[nf * 2 + 0];
            red[mw * 128 + nh * 64 + nf * 8 + lane * 2 + 1] = colp[nf * 2 + 1];
        }
    }
    __syncthreads();
    if (t < 128)
        g_dpart[(b * 16 + qt) * LS + kb + t] =
            (red[t] + red[128 + t]) + (red[256 + t] + red[384 + t]);
}

// ---------------- GEMM2: out = P . (inv*V)^T + c, pipelined, d-split -------
__global__ void __launch_bounds__(256, 3) ta_gemm2(float* __restrict__ out) {
    int qt = 15 - (blockIdx.x >> 1), dh = blockIdx.x & 1, b = blockIdx.y;
    int qb = qt << 7, db = dh << 6;
    int t = threadIdx.x, lane = t & 31, wid = t >> 5;

    if (g_qtflag[b * 16 + qt]) {               // out rows = c
        #pragma unroll
        for (int it = 0; it < 32; it++) {
            int idx = it * 256 + t;
            int r = idx >> 6, c = idx & 63;
            out[((size_t)(b * LS + qb + r)) * DD + db + c] = g_c[b * DD + db + c];
        }
        return;
    }

    extern __shared__ char smem[];
    int m0 = (wid & 3) * 32, n0 = (wid >> 2) * 32;
    float acc[2][4][4];
    #pragma unroll
    for (int i = 0; i < 2; i++)
        #pragma unroll
        for (int j = 0; j < 4; j++)
            #pragma unroll
            for (int v = 0; v < 4; v++) acc[i][j][v] = 0.f;

    const __half* Ph = g_Ph + ((size_t)(b * LS + qb)) * LS;
    const __half* Vh = g_Vth + ((size_t)(b * DD + db)) * LS;

    int nck = (qt + 1) * 2;
    load_tile_async<128>(Ph, LS, smem, t);
    load_tile_async<64>(Vh, LS, smem + G1_TB, t);
    CP_COMMIT();

    for (int ic = 0; ic < nck; ic++) {
        char* st = smem + (ic & 1) * G2_PV;
        if (ic + 1 < nck) {
            char* st2 = smem + ((ic + 1) & 1) * G2_PV;
            int kc2 = (ic + 1) * 64;
            load_tile_async<128>(Ph + kc2, LS, st2, t);
            load_tile_async<64>(Vh + kc2, LS, st2 + G1_TB, t);
            CP_COMMIT();
            CP_WAIT(1);
        } else {
            CP_WAIT(0);
        }
        __syncthreads();
        mma_pass<2>(st, st + G1_TB, lane, m0, n0, acc);
        __syncthreads();
    }

    int gid = lane >> 2, tid = lane & 3;
    #pragma unroll
    for (int mf = 0; mf < 2; mf++)
        #pragma unroll
        for (int h = 0; h < 2; h++) {
            int m = m0 + mf * 16 + h * 8 + gid;
            size_t ob = ((size_t)(b * LS + qb + m)) * DD;
            #pragma unroll
            for (int nf = 0; nf < 4; nf++) {
                int d = db + n0 + nf * 8 + tid * 2;
                float2 r;
                r.x = acc[mf][nf][h * 2 + 0] + g_c[b * DD + d];
                r.y = acc[mf][nf][h * 2 + 1] + g_c[b * DD + d + 1];
                *(float2*)&out[ob + d] = r;
            }
        }
}

// ---------------- launch ---------------------------------------------------
extern "C" void kernel_launch(void* const* d_in, const int* in_sizes, int n_in,
                              void* d_out, int out_size) {
    const int*   ci = (const int*)d_in[0];
    const float* qv = (const float*)d_in[1];   // cas_embs = Q = V
    const void*  mk = d_in[2];
    const float* te = (const float*)d_in[3];
    float* out = (float*)d_out;

    cudaFuncSetAttribute(ta_gemm1, cudaFuncAttributeMaxDynamicSharedMemorySize, G1_SMEM);
    cudaFuncSetAttribute(ta_gemm2, cudaFuncAttributeMaxDynamicSharedMemorySize, G2_SMEM);

    ta_detect<<<1, 256>>>((const unsigned int*)mk);
    ta_buildmask<<<(BB * LS) / 256, 256>>>(mk);
    ta_prep<<<(BB * LS * DD) / 256, 256>>>(ci, qv, te);
    ta_gemm1<<<dim3(136, BB), 256, G1_SMEM>>>();
    ta_dred<<<dim3(16, BB), 128>>>();
    ta_cpart<<<dim3(16, BB), 128>>>(qv);
    ta_cfin<<<BB, 128>>>();
    ta_vt<<<dim3(LS / 32, DD / 32, BB), dim3(32, 8)>>>(qv);
    ta_gemm2<<<dim3(32, BB), 256, G2_SMEM>>>(out);
}